// round 16
// baseline (speedup 1.0000x reference)
#include <cuda_runtime.h>
#include <cuda_bf16.h>
#include <math.h>
#include <stdint.h>

#define NSEQ 3072
#define EMB 768
#define NHEAD 12
#define DHEAD 64
#define NLAYER 4
#define FFDIM 3072

typedef __nv_bfloat16 bf16;

// -------------------- scratch (device globals; no allocations allowed) -----
__device__ float g_out[NSEQ * EMB];    // fp32: residual + final mean
__device__ float g_tmp[NSEQ * EMB];    // fp32: LN input
__device__ float g_xm[NSEQ * EMB];     // fp32: residual for FF2
// bf16 hi/lo activation planes
__device__ bf16 g_out_h[NSEQ * EMB], g_out_l[NSEQ * EMB];
__device__ bf16 g_xm_h[NSEQ * EMB],  g_xm_l[NSEQ * EMB];
__device__ bf16 g_q_h[NSEQ * EMB],   g_q_l[NSEQ * EMB];
__device__ bf16 g_k_h[NSEQ * EMB],   g_k_l[NSEQ * EMB];
__device__ bf16 g_v_h[NSEQ * EMB],   g_v_l[NSEQ * EMB];
__device__ bf16 g_att_h[NSEQ * EMB], g_att_l[NSEQ * EMB];
__device__ bf16 g_ff_h[NSEQ * FFDIM], g_ff_l[NSEQ * FFDIM];
// bf16 hi/lo weight planes (split once per launch)
__device__ bf16 g_wq_h[NLAYER * EMB * EMB],  g_wq_l[NLAYER * EMB * EMB];
__device__ bf16 g_wk_h[NLAYER * EMB * EMB],  g_wk_l[NLAYER * EMB * EMB];
__device__ bf16 g_wv_h[NLAYER * EMB * EMB],  g_wv_l[NLAYER * EMB * EMB];
__device__ bf16 g_wo_h[NLAYER * EMB * EMB],  g_wo_l[NLAYER * EMB * EMB];
__device__ bf16 g_w1_h[NLAYER * FFDIM * EMB], g_w1_l[NLAYER * FFDIM * EMB];
__device__ bf16 g_w2_h[NLAYER * EMB * FFDIM], g_w2_l[NLAYER * EMB * FFDIM];

// ==================== helpers ==============================================
__device__ __forceinline__ uint32_t smem_u32(const void* p) {
    uint32_t a;
    asm("{ .reg .u64 t; cvta.to.shared.u64 t, %1; cvt.u32.u64 %0, t; }" : "=r"(a) : "l"(p));
    return a;
}

#define CPA16(s, g) \
    asm volatile("cp.async.cg.shared.global [%0], [%1], 16;" :: "r"(s), "l"(g))
#define CPC() asm volatile("cp.async.commit_group;" ::: "memory")
#define CPW(N) asm volatile("cp.async.wait_group %0;" :: "n"(N) : "memory")

#define LDMX4(R, addr) \
    asm volatile("ldmatrix.sync.aligned.m8n8.x4.shared.b16 {%0,%1,%2,%3}, [%4];" \
        : "=r"((R)[0]), "=r"((R)[1]), "=r"((R)[2]), "=r"((R)[3]) : "r"(addr))

#define LDMX4T(R, addr) \
    asm volatile("ldmatrix.sync.aligned.m8n8.x4.trans.shared.b16 {%0,%1,%2,%3}, [%4];" \
        : "=r"((R)[0]), "=r"((R)[1]), "=r"((R)[2]), "=r"((R)[3]) : "r"(addr))

#define MMA16816(D, Af, B0, B1) \
    asm volatile("mma.sync.aligned.m16n8k16.row.col.f32.bf16.bf16.f32 " \
        "{%0,%1,%2,%3}, {%4,%5,%6,%7}, {%8,%9}, {%0,%1,%2,%3};" \
        : "+f"((D)[0]), "+f"((D)[1]), "+f"((D)[2]), "+f"((D)[3]) \
        : "r"((Af)[0]), "r"((Af)[1]), "r"((Af)[2]), "r"((Af)[3]), "r"(B0), "r"(B1))

// -------------------- hi/lo split kernel (weights) -------------------------
__global__ void conv_split(const float* __restrict__ src, bf16* __restrict__ h,
                           bf16* __restrict__ l, int n4)
{
    int i = blockIdx.x * 256 + threadIdx.x;
    if (i >= n4) return;
    float4 a = ((const float4*)src)[i];
    __nv_bfloat162 h0 = __floats2bfloat162_rn(a.x, a.y);
    __nv_bfloat162 h1 = __floats2bfloat162_rn(a.z, a.w);
    float2 f0 = __bfloat1622float2(h0);
    float2 f1 = __bfloat1622float2(h1);
    __nv_bfloat162 l0 = __floats2bfloat162_rn(a.x - f0.x, a.y - f0.y);
    __nv_bfloat162 l1 = __floats2bfloat162_rn(a.z - f1.x, a.w - f1.y);
    ((uint2*)h)[i] = make_uint2(*(uint32_t*)&h0, *(uint32_t*)&h1);
    ((uint2*)l)[i] = make_uint2(*(uint32_t*)&l0, *(uint32_t*)&l1);
}

// ==================== bf16x3 HMMA GEMM (cp.async double-buffered) ==========
// C[M,N] = (Ah+Al)[M,K] @ (Bh+Bl)[N,K]^T, 3-pass. M,N mult of 128, K of 32.
enum { MODE_BF16 = 0, MODE_RES = 2, MODE_BRELU = 3, MODE_BRES = 4 };

#define TSTR 40
#define GT_BYTES (128 * TSTR * 2)      // 10240 per tile
#define GEMM_DSMEM (8 * GT_BYTES)      // 2 stages x 4 tiles = 81920

template <int MODE>
__device__ __forceinline__ void gemm_core(
    const bf16* __restrict__ Ah, const bf16* __restrict__ Al,
    const bf16* __restrict__ Bh, const bf16* __restrict__ Bl,
    float* __restrict__ Cf, bf16* __restrict__ Ch, bf16* __restrict__ Cl,
    int N, int K, const float* __restrict__ bias, const float* __restrict__ extra)
{
    extern __shared__ char smraw[];
    const uint32_t smb = smem_u32(smraw);
    const int tid = threadIdx.x;
    const int lane = tid & 31;
    const int wid = tid >> 5;
    const int wm = (wid & 1) * 64;
    const int wn = (wid >> 1) * 32;
    const int bm = blockIdx.y * 128;
    const int bn = blockIdx.x * 128;
    const int sub = lane >> 3, r8 = lane & 7;

    const bf16* tb[4] = { Ah + (size_t)bm * K, Al + (size_t)bm * K,
                          Bh + (size_t)bn * K, Bl + (size_t)bn * K };

    float d[4][4][4];
#pragma unroll
    for (int i = 0; i < 4; i++)
#pragma unroll
        for (int j = 0; j < 4; j++)
#pragma unroll
            for (int k = 0; k < 4; k++) d[i][j][k] = 0.f;

    const int nch = K >> 5;

    // issue chunk c into stage s (one commit group)
#define G_ISSUE(c_, s_) do { \
        const int k0_ = (c_) << 5; \
        _Pragma("unroll") \
        for (int t_ = 0; t_ < 4; t_++) { \
            const bf16* src_ = tb[t_] + k0_; \
            uint32_t sb_ = smb + (uint32_t)((s_) * 4 + t_) * GT_BYTES; \
            _Pragma("unroll") \
            for (int i_ = 0; i_ < 2; i_++) { \
                int idx_ = i_ * 256 + tid; \
                int row_ = idx_ >> 2, seg_ = idx_ & 3; \
                CPA16(sb_ + (uint32_t)(row_ * TSTR + seg_ * 8) * 2, \
                      src_ + (size_t)row_ * K + seg_ * 8); \
            } \
        } \
        CPC(); \
    } while (0)

    G_ISSUE(0, 0);
    for (int c = 0; c < nch; c++) {
        if (c + 1 < nch) { G_ISSUE(c + 1, (c + 1) & 1); CPW(1); }
        else             { CPW(0); }
        __syncthreads();

        const uint32_t base = smb + (uint32_t)((c & 1) * 4) * GT_BYTES;
        const uint32_t aAhi = base;
        const uint32_t aAlo = base + GT_BYTES;
        const uint32_t aBhi = base + 2 * GT_BYTES;
        const uint32_t aBlo = base + 3 * GT_BYTES;

#pragma unroll
        for (int kf = 0; kf < 2; kf++) {
            uint32_t ahi[4][4], alo[4][4], bhi[2][4], blo[2][4];
#pragma unroll
            for (int mi = 0; mi < 4; mi++) {
                int row = wm + mi * 16 + (sub & 1) * 8 + r8;
                int col = kf * 16 + (sub >> 1) * 8;
                uint32_t off = (uint32_t)(row * TSTR + col) * 2;
                LDMX4(ahi[mi], aAhi + off);
                LDMX4(alo[mi], aAlo + off);
            }
#pragma unroll
            for (int np = 0; np < 2; np++) {
                int row = wn + np * 16 + (sub >> 1) * 8 + r8;
                int col = kf * 16 + (sub & 1) * 8;
                uint32_t off = (uint32_t)(row * TSTR + col) * 2;
                LDMX4(bhi[np], aBhi + off);
                LDMX4(blo[np], aBlo + off);
            }
#pragma unroll
            for (int mi = 0; mi < 4; mi++)
#pragma unroll
                for (int ni = 0; ni < 4; ni++) {
                    const uint32_t h0 = bhi[ni >> 1][(ni & 1) * 2];
                    const uint32_t h1 = bhi[ni >> 1][(ni & 1) * 2 + 1];
                    const uint32_t l0 = blo[ni >> 1][(ni & 1) * 2];
                    const uint32_t l1 = blo[ni >> 1][(ni & 1) * 2 + 1];
                    MMA16816(d[mi][ni], ahi[mi], h0, h1);
                    MMA16816(d[mi][ni], ahi[mi], l0, l1);
                    MMA16816(d[mi][ni], alo[mi], h0, h1);
                }
        }
        __syncthreads();
    }
#undef G_ISSUE

    // ---- epilogue ----
    const int er = lane >> 2, ec = (lane & 3) * 2;
#pragma unroll
    for (int mi = 0; mi < 4; mi++)
#pragma unroll
        for (int ni = 0; ni < 4; ni++) {
            const int col = bn + wn + ni * 8 + ec;
#pragma unroll
            for (int half = 0; half < 2; half++) {
                const int row = bm + wm + mi * 16 + er + half * 8;
                float2 v = make_float2(d[mi][ni][half * 2], d[mi][ni][half * 2 + 1]);
                if (MODE == MODE_RES) {
                    float2 e = *(const float2*)(extra + (size_t)row * N + col);
                    v.x += e.x; v.y += e.y;
                    *(float2*)(Cf + (size_t)row * N + col) = v;
                } else if (MODE == MODE_BRES) {
                    float2 e = *(const float2*)(extra + (size_t)row * N + col);
                    v.x += bias[col] + e.x;
                    v.y += bias[col + 1] + e.y;
                    *(float2*)(Cf + (size_t)row * N + col) = v;
                } else {
                    if (MODE == MODE_BRELU) {
                        v.x = fmaxf(v.x + bias[col], 0.f);
                        v.y = fmaxf(v.y + bias[col + 1], 0.f);
                    }
                    __nv_bfloat162 h = __floats2bfloat162_rn(v.x, v.y);
                    float2 hf = __bfloat1622float2(h);
                    __nv_bfloat162 lo = __floats2bfloat162_rn(v.x - hf.x, v.y - hf.y);
                    *(uint32_t*)(Ch + (size_t)row * N + col) = *(uint32_t*)&h;
                    *(uint32_t*)(Cl + (size_t)row * N + col) = *(uint32_t*)&lo;
                }
            }
        }
}

template <int MODE>
__global__ __launch_bounds__(256, 1) void mma_gemm(
    const bf16* __restrict__ Ah, const bf16* __restrict__ Al,
    const bf16* __restrict__ Bh, const bf16* __restrict__ Bl,
    float* __restrict__ Cf, bf16* __restrict__ Ch, bf16* __restrict__ Cl,
    int N, int K, const float* __restrict__ bias, const float* __restrict__ extra)
{
    gemm_core<MODE>(Ah, Al, Bh, Bl, Cf, Ch, Cl, N, K, bias, extra);
}

__global__ __launch_bounds__(256, 1) void mma_qkv(
    const bf16* __restrict__ Ah, const bf16* __restrict__ Al,
    const bf16* wqh, const bf16* wql, const bf16* wkh, const bf16* wkl,
    const bf16* wvh, const bf16* wvl,
    bf16* qh, bf16* ql, bf16* kh, bf16* kl, bf16* vh, bf16* vl)
{
    const bf16* Bh = (blockIdx.z == 0) ? wqh : (blockIdx.z == 1) ? wkh : wvh;
    const bf16* Bl = (blockIdx.z == 0) ? wql : (blockIdx.z == 1) ? wkl : wvl;
    bf16* Ch = (blockIdx.z == 0) ? qh : (blockIdx.z == 1) ? kh : vh;
    bf16* Cl = (blockIdx.z == 0) ? ql : (blockIdx.z == 1) ? kl : vl;
    gemm_core<MODE_BF16>(Ah, Al, Bh, Bl, nullptr, Ch, Cl, EMB, EMB, nullptr, nullptr);
}

// ==================== HMMA flash attention (cp.async double-buffered) ======
#define FTSTR 72
#define FT_BYTES (128 * FTSTR * 2)     // 18432
#define FSTG (3 * FT_BYTES)            // 55296 per stage {Khi, Klo, V}
#define FLASH_DSMEM (2 * FSTG)         // 110592

__global__ __launch_bounds__(256, 1) void flash_hmma(
    const bf16* __restrict__ Qh, const bf16* __restrict__ Ql,
    const bf16* __restrict__ Kh, const bf16* __restrict__ Kl,
    const bf16* __restrict__ Vh,
    bf16* __restrict__ Oh, bf16* __restrict__ Ol)
{
    extern __shared__ char smraw[];
    const uint32_t smb = smem_u32(smraw);
    const int tid = threadIdx.x;
    const int lane = tid & 31;
    const int wid = tid >> 5;
    const int sub = lane >> 3, r8 = lane & 7;
    const int er = lane >> 2, ec = (lane & 3) * 2;
    const int wm = wid * 16;
    const int q0 = blockIdx.x * 128;
    const int hoff = blockIdx.y * DHEAD;
    const float rscale = 0.03608439182435161f;  // 1/sqrt(768)

#define F_ISSUE_KV(kb_, s_) do { \
        const bf16* ks_[3] = { Kh + (size_t)(kb_) * EMB + hoff, \
                               Kl + (size_t)(kb_) * EMB + hoff, \
                               Vh + (size_t)(kb_) * EMB + hoff }; \
        uint32_t base_ = smb + (uint32_t)(s_) * FSTG; \
        _Pragma("unroll") \
        for (int t_ = 0; t_ < 3; t_++) { \
            uint32_t sb_ = base_ + (uint32_t)t_ * FT_BYTES; \
            const bf16* src_ = ks_[t_]; \
            _Pragma("unroll") \
            for (int i_ = 0; i_ < 4; i_++) { \
                int idx_ = i_ * 256 + tid; \
                int row_ = idx_ >> 3, seg_ = idx_ & 7; \
                CPA16(sb_ + (uint32_t)(row_ * FTSTR + seg_ * 8) * 2, \
                      src_ + (size_t)row_ * EMB + seg_ * 8); \
            } \
        } \
        CPC(); \
    } while (0)

    // ---- stage Q into stage1 {Khi, Klo} slots, prefetch kv tile 0 ----
    {
        const bf16* s0 = Qh + (size_t)q0 * EMB + hoff;
        const bf16* s1 = Ql + (size_t)q0 * EMB + hoff;
        uint32_t b0 = smb + FSTG;
        uint32_t b1 = smb + FSTG + FT_BYTES;
#pragma unroll
        for (int i = 0; i < 4; i++) {
            int idx = i * 256 + tid;
            int row = idx >> 3, seg = idx & 7;
            uint32_t so = (uint32_t)(row * FTSTR + seg * 8) * 2;
            CPA16(b0 + so, s0 + (size_t)row * EMB + seg * 8);
            CPA16(b1 + so, s1 + (size_t)row * EMB + seg * 8);
        }
        CPC();
    }
    F_ISSUE_KV(0, 0);
    CPW(1);
    __syncthreads();

    // ---- extract Q fragments from stage1 ----
    uint32_t qhi[4][4], qlo[4][4];
    {
        const uint32_t aQh = smb + FSTG;
        const uint32_t aQl = smb + FSTG + FT_BYTES;
#pragma unroll
        for (int kf = 0; kf < 4; kf++) {
            uint32_t off = (uint32_t)((wm + (sub & 1) * 8 + r8) * FTSTR
                                      + kf * 16 + (sub >> 1) * 8) * 2;
            LDMX4(qhi[kf], aQh + off);
            LDMX4(qlo[kf], aQl + off);
        }
    }
    __syncthreads();

    float o[8][4];
#pragma unroll
    for (int i = 0; i < 8; i++)
#pragma unroll
        for (int j = 0; j < 4; j++) o[i][j] = 0.f;
    float m0 = -INFINITY, m1 = -INFINITY, l0 = 0.f, l1 = 0.f;

    const int NT = NSEQ / 128;
    for (int it = 0; it < NT; it++) {
        if (it + 1 < NT) { F_ISSUE_KV((it + 1) * 128, (it + 1) & 1); CPW(1); }
        else             { CPW(0); }
        __syncthreads();

        const uint32_t base = smb + (uint32_t)(it & 1) * FSTG;
        const uint32_t aKhi = base;
        const uint32_t aKlo = base + FT_BYTES;
        const uint32_t aVt  = base + 2 * FT_BYTES;

        // ---- S = Q*K^T (3-pass hi/lo) ----
        float s[16][4];
#pragma unroll
        for (int ni = 0; ni < 16; ni++)
#pragma unroll
            for (int j = 0; j < 4; j++) s[ni][j] = 0.f;

#pragma unroll
        for (int kf = 0; kf < 4; kf++) {
#pragma unroll
            for (int np = 0; np < 8; np++) {
                uint32_t bh[4], bl[4];
                uint32_t off = (uint32_t)((np * 16 + (sub >> 1) * 8 + r8) * FTSTR
                                          + kf * 16 + (sub & 1) * 8) * 2;
                LDMX4(bh, aKhi + off);
                LDMX4(bl, aKlo + off);
                MMA16816(s[2 * np],     qhi[kf], bh[0], bh[1]);
                MMA16816(s[2 * np],     qhi[kf], bl[0], bl[1]);
                MMA16816(s[2 * np],     qlo[kf], bh[0], bh[1]);
                MMA16816(s[2 * np + 1], qhi[kf], bh[2], bh[3]);
                MMA16816(s[2 * np + 1], qhi[kf], bl[2], bl[3]);
                MMA16816(s[2 * np + 1], qlo[kf], bh[2], bh[3]);
            }
        }

        // ---- scale logits, online softmax ----
        float mx0 = -INFINITY, mx1 = -INFINITY;
#pragma unroll
        for (int ni = 0; ni < 16; ni++) {
            s[ni][0] *= rscale; s[ni][1] *= rscale;
            s[ni][2] *= rscale; s[ni][3] *= rscale;
            mx0 = fmaxf(mx0, fmaxf(s[ni][0], s[ni][1]));
            mx1 = fmaxf(mx1, fmaxf(s[ni][2], s[ni][3]));
        }
#pragma unroll
        for (int msk = 1; msk < 4; msk <<= 1) {
            mx0 = fmaxf(mx0, __shfl_xor_sync(0xffffffffu, mx0, msk));
            mx1 = fmaxf(mx1, __shfl_xor_sync(0xffffffffu, mx1, msk));
        }
        float mn0 = fmaxf(m0, mx0), mn1 = fmaxf(m1, mx1);
        float c0 = __expf(m0 - mn0), c1 = __expf(m1 - mn1);
        float rs0 = 0.f, rs1 = 0.f;
#pragma unroll
        for (int ni = 0; ni < 16; ni++) {
            s[ni][0] = __expf(s[ni][0] - mn0); rs0 += s[ni][0];
            s[ni][1] = __expf(s[ni][1] - mn0); rs0 += s[ni][1];
            s[ni][2] = __expf(s[ni][2] - mn1); rs1 += s[ni][2];
            s[ni][3] = __expf(s[ni][3] - mn1); rs1 += s[ni][3];
        }
#pragma unroll
        for (int msk = 1; msk < 4; msk <<= 1) {
            rs0 += __shfl_xor_sync(0xffffffffu, rs0, msk);
            rs1 += __shfl_xor_sync(0xffffffffu, rs1, msk);
        }
        l0 = l0 * c0 + rs0;
        l1 = l1 * c1 + rs1;
        m0 = mn0; m1 = mn1;
#pragma unroll
        for (int nd = 0; nd < 8; nd++) {
            o[nd][0] *= c0; o[nd][1] *= c0;
            o[nd][2] *= c1; o[nd][3] *= c1;
        }

        // ---- O += P*V (P from accum regs; V plain bf16) ----
#pragma unroll
        for (int kq = 0; kq < 8; kq++) {
            uint32_t pa[4];
            __nv_bfloat162 t;
            t = __floats2bfloat162_rn(s[2 * kq][0],     s[2 * kq][1]);     pa[0] = *(uint32_t*)&t;
            t = __floats2bfloat162_rn(s[2 * kq][2],     s[2 * kq][3]);     pa[1] = *(uint32_t*)&t;
            t = __floats2bfloat162_rn(s[2 * kq + 1][0], s[2 * kq + 1][1]); pa[2] = *(uint32_t*)&t;
            t = __floats2bfloat162_rn(s[2 * kq + 1][2], s[2 * kq + 1][3]); pa[3] = *(uint32_t*)&t;
#pragma unroll
            for (int nd16 = 0; nd16 < 4; nd16++) {
                uint32_t vb[4];
                uint32_t off = (uint32_t)((kq * 16 + (sub & 1) * 8 + r8) * FTSTR
                                          + nd16 * 16 + (sub >> 1) * 8) * 2;
                LDMX4T(vb, aVt + off);
                MMA16816(o[nd16 * 2],     pa, vb[0], vb[1]);
                MMA16816(o[nd16 * 2 + 1], pa, vb[2], vb[3]);
            }
        }
        __syncthreads();
    }
#undef F_ISSUE_KV

    // ---- write O as hi/lo bf16 planes ----
    const float inv0 = 1.0f / l0, inv1 = 1.0f / l1;
    const int row0 = q0 + wm + er, row1 = row0 + 8;
#pragma unroll
    for (int nd = 0; nd < 8; nd++) {
        const int col = hoff + nd * 8 + ec;
        float2 a0 = make_float2(o[nd][0] * inv0, o[nd][1] * inv0);
        float2 a1 = make_float2(o[nd][2] * inv1, o[nd][3] * inv1);
        __nv_bfloat162 h0 = __floats2bfloat162_rn(a0.x, a0.y);
        __nv_bfloat162 h1 = __floats2bfloat162_rn(a1.x, a1.y);
        float2 hf0 = __bfloat1622float2(h0);
        float2 hf1 = __bfloat1622float2(h1);
        __nv_bfloat162 lo0 = __floats2bfloat162_rn(a0.x - hf0.x, a0.y - hf0.y);
        __nv_bfloat162 lo1 = __floats2bfloat162_rn(a1.x - hf1.x, a1.y - hf1.y);
        *(uint32_t*)(Oh + (size_t)row0 * EMB + col) = *(uint32_t*)&h0;
        *(uint32_t*)(Ol + (size_t)row0 * EMB + col) = *(uint32_t*)&lo0;
        *(uint32_t*)(Oh + (size_t)row1 * EMB + col) = *(uint32_t*)&h1;
        *(uint32_t*)(Ol + (size_t)row1 * EMB + col) = *(uint32_t*)&lo1;
    }
}

// -------------------- fp32 SGEMM (embed only: trunc is discontinuous) ------
__global__ __launch_bounds__(256, 1) void sgemm_embed(
    const float* __restrict__ A, const float* __restrict__ B, float* __restrict__ C,
    bf16* __restrict__ Ch, bf16* __restrict__ Cl,
    int M, int N, int K, const float* __restrict__ bias, const float* __restrict__ extra)
{
    __shared__ float As[8][128];
    __shared__ float Bs[8][128];
    const int tid = threadIdx.x;
    const int bm = blockIdx.y * 128;
    const int bn = blockIdx.x * 128;
    const int lr = tid & 127;
    const int lc = (tid >> 7) << 2;
    const float* Ap = A + (size_t)(bm + lr) * K + lc;
    const float* Bp = B + (size_t)(bn + lr) * K + lc;
    const int tx = tid & 15, ty = tid >> 4;

    float acc[8][8];
#pragma unroll
    for (int i = 0; i < 8; i++)
#pragma unroll
        for (int j = 0; j < 8; j++) acc[i][j] = 0.f;

    for (int k0 = 0; k0 < K; k0 += 8) {
        float4 a4 = *(const float4*)(Ap + k0);
        float4 b4 = *(const float4*)(Bp + k0);
        As[lc + 0][lr] = a4.x; As[lc + 1][lr] = a4.y;
        As[lc + 2][lr] = a4.z; As[lc + 3][lr] = a4.w;
        Bs[lc + 0][lr] = b4.x; Bs[lc + 1][lr] = b4.y;
        Bs[lc + 2][lr] = b4.z; Bs[lc + 3][lr] = b4.w;
        __syncthreads();
#pragma unroll
        for (int k = 0; k < 8; k++) {
            float ra[8], rb[8];
            *(float4*)(ra)     = *(const float4*)&As[k][ty * 8];
            *(float4*)(ra + 4) = *(const float4*)&As[k][ty * 8 + 4];
            *(float4*)(rb)     = *(const float4*)&Bs[k][tx * 8];
            *(float4*)(rb + 4) = *(const float4*)&Bs[k][tx * 8 + 4];
#pragma unroll
            for (int i = 0; i < 8; i++)
#pragma unroll
                for (int j = 0; j < 8; j++)
                    acc[i][j] = fmaf(ra[i], rb[j], acc[i][j]);
        }
        __syncthreads();
    }

#pragma unroll
    for (int i = 0; i < 8; i++) {
        const int r = bm + ty * 8 + i;
#pragma unroll
        for (int j = 0; j < 8; j++) {
            const int c = bn + tx * 8 + j;
            float v = truncf(acc[i][j] + bias[c]) + extra[(size_t)r * N + c];
            C[(size_t)r * N + c] = v;
            bf16 h = __float2bfloat16(v);
            Ch[(size_t)r * N + c] = h;
            Cl[(size_t)r * N + c] = __float2bfloat16(v - __bfloat162float(h));
        }
    }
}

// -------------------- layernorm (fp32 + hi/lo outputs) ---------------------
__global__ __launch_bounds__(256, 1) void ln_kernel(
    const float* __restrict__ in, float* __restrict__ out,
    bf16* __restrict__ outh, bf16* __restrict__ outl,
    const float* __restrict__ g, const float* __restrict__ b)
{
    __shared__ float rs[8], rs2[8];
    __shared__ float s_mu, s_rstd;
    const int r = blockIdx.x;
    const int tid = threadIdx.x;
    const float* row = in + (size_t)r * EMB;
    float v0 = row[tid], v1 = row[tid + 256], v2 = row[tid + 512];
    float s = v0 + v1 + v2;
    float s2 = v0 * v0 + v1 * v1 + v2 * v2;
#pragma unroll
    for (int m = 16; m; m >>= 1) {
        s += __shfl_xor_sync(0xffffffffu, s, m);
        s2 += __shfl_xor_sync(0xffffffffu, s2, m);
    }
    if ((tid & 31) == 0) { rs[tid >> 5] = s; rs2[tid >> 5] = s2; }
    __syncthreads();
    if (tid == 0) {
        float S = 0.f, S2 = 0.f;
#pragma unroll
        for (int i = 0; i < 8; i++) { S += rs[i]; S2 += rs2[i]; }
        float mu = S * (1.0f / EMB);
        float var = S2 * (1.0f / EMB) - mu * mu;
        s_mu = mu;
        s_rstd = rsqrtf(var + 1e-5f);
    }
    __syncthreads();
    float mu = s_mu, rstd = s_rstd;
#pragma unroll
    for (int seg = 0; seg < 3; seg++) {
        int c = tid + seg * 256;
        float v = (seg == 0) ? v0 : (seg == 1) ? v1 : v2;
        float y = (v - mu) * rstd * g[c] + b[c];
        out[(size_t)r * EMB + c] = y;
        bf16 h = __float2bfloat16(y);
        outh[(size_t)r * EMB + c] = h;
        outl[(size_t)r * EMB + c] = __float2bfloat16(y - __bfloat162float(h));
    }
}

// -------------------- mean over sequence -----------------------------------
__global__ void mean_kernel(const float* __restrict__ in, float* __restrict__ out)
{
    int e = blockIdx.x * 256 + threadIdx.x;
    float s = 0.f;
    for (int n = 0; n < NSEQ; n++) s += in[(size_t)n * EMB + e];
    out[e] = s * (1.0f / NSEQ);
}

// -------------------- launch ------------------------------------------------
extern "C" void kernel_launch(void* const* d_in, const int* in_sizes, int n_in,
                              void* d_out, int out_size)
{
    (void)in_sizes; (void)n_in; (void)out_size;
    const float* x      = (const float*)d_in[0];
    const float* W_word = (const float*)d_in[2];
    const float* b_word = (const float*)d_in[3];
    const float* pos    = (const float*)d_in[4];
    const float* Wq     = (const float*)d_in[5];
    const float* Wk     = (const float*)d_in[6];
    const float* Wv     = (const float*)d_in[7];
    const float* Wo     = (const float*)d_in[8];
    const float* W1     = (const float*)d_in[9];
    const float* b1     = (const float*)d_in[10];
    const float* W2     = (const float*)d_in[11];
    const float* b2     = (const float*)d_in[12];
    const float* g1     = (const float*)d_in[13];
    const float* be1    = (const float*)d_in[14];
    const float* g2     = (const float*)d_in[15];
    const float* be2    = (const float*)d_in[16];
    float* out = (float*)d_out;

    float *p_out, *p_tmp, *p_xm;
    bf16 *p_out_h, *p_out_l, *p_xm_h, *p_xm_l;
    bf16 *p_q_h, *p_q_l, *p_k_h, *p_k_l, *p_v_h, *p_v_l, *p_att_h, *p_att_l;
    bf16 *p_ff_h, *p_ff_l;
    bf16 *p_wq_h, *p_wq_l, *p_wk_h, *p_wk_l, *p_wv_h, *p_wv_l;
    bf16 *p_wo_h, *p_wo_l, *p_w1_h, *p_w1_l, *p_w2_h, *p_w2_l;
    cudaGetSymbolAddress((void**)&p_out, g_out);
    cudaGetSymbolAddress((void**)&p_tmp, g_tmp);
    cudaGetSymbolAddress((void**)&p_xm,  g_xm);
    cudaGetSymbolAddress((void**)&p_out_h, g_out_h); cudaGetSymbolAddress((void**)&p_out_l, g_out_l);
    cudaGetSymbolAddress((void**)&p_xm_h,  g_xm_h);  cudaGetSymbolAddress((void**)&p_xm_l,  g_xm_l);
    cudaGetSymbolAddress((void**)&p_q_h,   g_q_h);   cudaGetSymbolAddress((void**)&p_q_l,   g_q_l);
    cudaGetSymbolAddress((void**)&p_k_h,   g_k_h);   cudaGetSymbolAddress((void**)&p_k_l,   g_k_l);
    cudaGetSymbolAddress((void**)&p_v_h,   g_v_h);   cudaGetSymbolAddress((void**)&p_v_l,   g_v_l);
    cudaGetSymbolAddress((void**)&p_att_h, g_att_h); cudaGetSymbolAddress((void**)&p_att_l, g_att_l);
    cudaGetSymbolAddress((void**)&p_ff_h,  g_ff_h);  cudaGetSymbolAddress((void**)&p_ff_l,  g_ff_l);
    cudaGetSymbolAddress((void**)&p_wq_h, g_wq_h);   cudaGetSymbolAddress((void**)&p_wq_l, g_wq_l);
    cudaGetSymbolAddress((void**)&p_wk_h, g_wk_h);   cudaGetSymbolAddress((void**)&p_wk_l, g_wk_l);
    cudaGetSymbolAddress((void**)&p_wv_h, g_wv_h);   cudaGetSymbolAddress((void**)&p_wv_l, g_wv_l);
    cudaGetSymbolAddress((void**)&p_wo_h, g_wo_h);   cudaGetSymbolAddress((void**)&p_wo_l, g_wo_l);
    cudaGetSymbolAddress((void**)&p_w1_h, g_w1_h);   cudaGetSymbolAddress((void**)&p_w1_l, g_w1_l);
    cudaGetSymbolAddress((void**)&p_w2_h, g_w2_h);   cudaGetSymbolAddress((void**)&p_w2_l, g_w2_l);

    cudaFuncSetAttribute(mma_gemm<MODE_RES>,   cudaFuncAttributeMaxDynamicSharedMemorySize, GEMM_DSMEM);
    cudaFuncSetAttribute(mma_gemm<MODE_BRELU>, cudaFuncAttributeMaxDynamicSharedMemorySize, GEMM_DSMEM);
    cudaFuncSetAttribute(mma_gemm<MODE_BRES>,  cudaFuncAttributeMaxDynamicSharedMemorySize, GEMM_DSMEM);
    cudaFuncSetAttribute(mma_qkv,              cudaFuncAttributeMaxDynamicSharedMemorySize, GEMM_DSMEM);
    cudaFuncSetAttribute(flash_hmma,           cudaFuncAttributeMaxDynamicSharedMemorySize, FLASH_DSMEM);

    // ---- split weights into hi/lo planes (once per launch) ----
    {
        int nee4 = NLAYER * EMB * EMB / 4;
        int nfe4 = NLAYER * FFDIM * EMB / 4;
        conv_split<<<(nee4 + 255) / 256, 256>>>(Wq, p_wq_h, p_wq_l, nee4);
        conv_split<<<(nee4 + 255) / 256, 256>>>(Wk, p_wk_h, p_wk_l, nee4);
        conv_split<<<(nee4 + 255) / 256, 256>>>(Wv, p_wv_h, p_wv_l, nee4);
        conv_split<<<(nee4 + 255) / 256, 256>>>(Wo, p_wo_h, p_wo_l, nee4);
        conv_split<<<(nfe4 + 255) / 256, 256>>>(W1, p_w1_h, p_w1_l, nfe4);
        conv_split<<<(nfe4 + 255) / 256, 256>>>(W2, p_w2_h, p_w2_l, nfe4);
    }

    dim3 blk(256);
    dim3 gEE(EMB / 128, NSEQ / 128);       // 6 x 24
    dim3 gQKV(EMB / 128, NSEQ / 128, 3);   // 6 x 24 x 3
    dim3 gFF(FFDIM / 128, NSEQ / 128);     // 24 x 24
    dim3 gFL(NSEQ / 128, NHEAD);           // 24 x 12

    // embed: out = trunc(x @ Ww^T + b_word) + pos (fp32 + hi/lo planes)
    sgemm_embed<<<gEE, blk>>>(x, W_word, p_out, p_out_h, p_out_l,
                              NSEQ, EMB, EMB, b_word, pos);

    for (int l = 0; l < NLAYER; l++) {
        const size_t oEE = (size_t)l * EMB * EMB;
        const size_t oFE = (size_t)l * FFDIM * EMB;

        mma_qkv<<<gQKV, blk, GEMM_DSMEM>>>(
            p_out_h, p_out_l,
            p_wq_h + oEE, p_wq_l + oEE, p_wk_h + oEE, p_wk_l + oEE,
            p_wv_h + oEE, p_wv_l + oEE,
            p_q_h, p_q_l, p_k_h, p_k_l, p_v_h, p_v_l);

        flash_hmma<<<gFL, blk, FLASH_DSMEM>>>(
            p_q_h, p_q_l, p_k_h, p_k_l, p_v_h, p_att_h, p_att_l);

        mma_gemm<MODE_RES><<<gEE, blk, GEMM_DSMEM>>>(
            p_att_h, p_att_l, p_wo_h + oEE, p_wo_l + oEE,
            p_tmp, nullptr, nullptr, EMB, EMB, nullptr, p_out);
        ln_kernel<<<NSEQ, 256>>>(p_tmp, p_xm, p_xm_h, p_xm_l,
                                 g1 + (size_t)l * EMB, be1 + (size_t)l * EMB);

        mma_gemm<MODE_BRELU><<<gFF, blk, GEMM_DSMEM>>>(
            p_xm_h, p_xm_l, p_w1_h + oFE, p_w1_l + oFE,
            nullptr, p_ff_h, p_ff_l, FFDIM, EMB, b1 + (size_t)l * FFDIM, nullptr);
        mma_gemm<MODE_BRES><<<gEE, blk, GEMM_DSMEM>>>(
            p_ff_h, p_ff_l, p_w2_h + oFE, p_w2_l + oFE,
            p_tmp, nullptr, nullptr, EMB, FFDIM, b2 + (size_t)l * EMB, p_xm);
        ln_kernel<<<NSEQ, 256>>>(p_tmp, p_out, p_out_h, p_out_l,
                                 g2 + (size_t)l * EMB, be2 + (size_t)l * EMB);
    }

    mean_kernel<<<3, 256>>>(p_out, out);
}

// round 17
// speedup vs baseline: 1.6391x; 1.6391x over previous
#include <cuda_runtime.h>
#include <cuda_bf16.h>
#include <math.h>
#include <stdint.h>

#define NSEQ 3072
#define EMB 768
#define NHEAD 12
#define DHEAD 64
#define NLAYER 4
#define FFDIM 3072

typedef __nv_bfloat16 bf16;

// -------------------- scratch (device globals; no allocations allowed) -----
__device__ float g_out[NSEQ * EMB];    // fp32: residual + final mean
__device__ float g_tmp[NSEQ * EMB];    // fp32: LN input
__device__ float g_xm[NSEQ * EMB];     // fp32: residual for FF2
// bf16 hi/lo activation planes
__device__ bf16 g_out_h[NSEQ * EMB], g_out_l[NSEQ * EMB];
__device__ bf16 g_xm_h[NSEQ * EMB],  g_xm_l[NSEQ * EMB];
__device__ bf16 g_q_h[NSEQ * EMB],   g_q_l[NSEQ * EMB];
__device__ bf16 g_k_h[NSEQ * EMB],   g_k_l[NSEQ * EMB];
__device__ bf16 g_v_h[NSEQ * EMB],   g_v_l[NSEQ * EMB];
__device__ bf16 g_att_h[NSEQ * EMB], g_att_l[NSEQ * EMB];
__device__ bf16 g_ff_h[NSEQ * FFDIM], g_ff_l[NSEQ * FFDIM];
// bf16 hi/lo weight planes (split once per launch)
__device__ bf16 g_wq_h[NLAYER * EMB * EMB],  g_wq_l[NLAYER * EMB * EMB];
__device__ bf16 g_wk_h[NLAYER * EMB * EMB],  g_wk_l[NLAYER * EMB * EMB];
__device__ bf16 g_wv_h[NLAYER * EMB * EMB],  g_wv_l[NLAYER * EMB * EMB];
__device__ bf16 g_wo_h[NLAYER * EMB * EMB],  g_wo_l[NLAYER * EMB * EMB];
__device__ bf16 g_w1_h[NLAYER * FFDIM * EMB], g_w1_l[NLAYER * FFDIM * EMB];
__device__ bf16 g_w2_h[NLAYER * EMB * FFDIM], g_w2_l[NLAYER * EMB * FFDIM];

// ==================== helpers ==============================================
__device__ __forceinline__ uint32_t smem_u32(const void* p) {
    uint32_t a;
    asm("{ .reg .u64 t; cvta.to.shared.u64 t, %1; cvt.u32.u64 %0, t; }" : "=r"(a) : "l"(p));
    return a;
}

#define LDMX4(R, addr) \
    asm volatile("ldmatrix.sync.aligned.m8n8.x4.shared.b16 {%0,%1,%2,%3}, [%4];" \
        : "=r"((R)[0]), "=r"((R)[1]), "=r"((R)[2]), "=r"((R)[3]) : "r"(addr))

#define LDMX4T(R, addr) \
    asm volatile("ldmatrix.sync.aligned.m8n8.x4.trans.shared.b16 {%0,%1,%2,%3}, [%4];" \
        : "=r"((R)[0]), "=r"((R)[1]), "=r"((R)[2]), "=r"((R)[3]) : "r"(addr))

#define MMA16816(D, Af, B0, B1) \
    asm volatile("mma.sync.aligned.m16n8k16.row.col.f32.bf16.bf16.f32 " \
        "{%0,%1,%2,%3}, {%4,%5,%6,%7}, {%8,%9}, {%0,%1,%2,%3};" \
        : "+f"((D)[0]), "+f"((D)[1]), "+f"((D)[2]), "+f"((D)[3]) \
        : "r"((Af)[0]), "r"((Af)[1]), "r"((Af)[2]), "r"((Af)[3]), "r"(B0), "r"(B1))

// -------------------- hi/lo split kernel (weights) -------------------------
__global__ void conv_split(const float* __restrict__ src, bf16* __restrict__ h,
                           bf16* __restrict__ l, int n4)
{
    int i = blockIdx.x * 256 + threadIdx.x;
    if (i >= n4) return;
    float4 a = ((const float4*)src)[i];
    __nv_bfloat162 h0 = __floats2bfloat162_rn(a.x, a.y);
    __nv_bfloat162 h1 = __floats2bfloat162_rn(a.z, a.w);
    float2 f0 = __bfloat1622float2(h0);
    float2 f1 = __bfloat1622float2(h1);
    __nv_bfloat162 l0 = __floats2bfloat162_rn(a.x - f0.x, a.y - f0.y);
    __nv_bfloat162 l1 = __floats2bfloat162_rn(a.z - f1.x, a.w - f1.y);
    ((uint2*)h)[i] = make_uint2(*(uint32_t*)&h0, *(uint32_t*)&h1);
    ((uint2*)l)[i] = make_uint2(*(uint32_t*)&l0, *(uint32_t*)&l1);
}

// ==================== bf16x3 HMMA GEMM (reg-staged LDG double buffer) ======
// C[M,N] = (Ah+Al)[M,K] @ (Bh+Bl)[N,K]^T, 3-pass. M,N mult of 128, K of 32.
enum { MODE_BF16 = 0, MODE_RES = 2, MODE_BRELU = 3, MODE_BRES = 4 };

#define TSTR 40
#define GT_HALFS (128 * TSTR)
#define GT_BYTES (GT_HALFS * 2)        // 10240 per tile
#define GEMM_DSMEM (8 * GT_BYTES)      // 2 stages x 4 tiles = 81920

template <int MODE>
__device__ __forceinline__ void gemm_core(
    const bf16* __restrict__ Ah, const bf16* __restrict__ Al,
    const bf16* __restrict__ Bh, const bf16* __restrict__ Bl,
    float* __restrict__ Cf, bf16* __restrict__ Ch, bf16* __restrict__ Cl,
    int N, int K, const float* __restrict__ bias, const float* __restrict__ extra)
{
    extern __shared__ char smraw[];
    bf16* smem = (bf16*)smraw;
    const int tid = threadIdx.x;
    const int lane = tid & 31;
    const int wid = tid >> 5;
    const int wm = (wid & 1) * 64;
    const int wn = (wid >> 1) * 32;
    const int bm = blockIdx.y * 128;
    const int bn = blockIdx.x * 128;
    const int sub = lane >> 3, r8 = lane & 7;

    const bf16* tb[4] = { Ah + (size_t)bm * K, Al + (size_t)bm * K,
                          Bh + (size_t)bn * K, Bl + (size_t)bn * K };

    // per-thread copy coordinates: 2 uint4 per tile (128x32 halfs per tile)
    const int fr = tid >> 2;              // 0..63
    const int fs = (tid & 3) * 8;         // 0,8,16,24 halfs

    float d[4][4][4];
#pragma unroll
    for (int i = 0; i < 4; i++)
#pragma unroll
        for (int j = 0; j < 4; j++)
#pragma unroll
            for (int k = 0; k < 4; k++) d[i][j][k] = 0.f;

    uint4 st[8];
#define G_FETCH(k0_) do { \
        _Pragma("unroll") \
        for (int t_ = 0; t_ < 4; t_++) \
            _Pragma("unroll") \
            for (int i_ = 0; i_ < 2; i_++) \
                st[t_ * 2 + i_] = *(const uint4*)(tb[t_] + (size_t)(fr + i_ * 64) * K + (k0_) + fs); \
    } while (0)
#define G_COMMIT(s_) do { \
        _Pragma("unroll") \
        for (int t_ = 0; t_ < 4; t_++) { \
            bf16* dst_ = smem + (size_t)((s_) * 4 + t_) * GT_HALFS; \
            _Pragma("unroll") \
            for (int i_ = 0; i_ < 2; i_++) { \
                int off_ = (fr + i_ * 64) * TSTR + fs; \
                uint4 v_ = st[t_ * 2 + i_]; \
                *(uint2*)(dst_ + off_)     = make_uint2(v_.x, v_.y); \
                *(uint2*)(dst_ + off_ + 4) = make_uint2(v_.z, v_.w); \
            } \
        } \
    } while (0)

    const int nch = K >> 5;
    G_FETCH(0);
    G_COMMIT(0);
    __syncthreads();

    for (int c = 0; c < nch; c++) {
        const bool more = (c + 1 < nch);
        if (more) G_FETCH((c + 1) << 5);

        const uint32_t base = smem_u32(smem) + (uint32_t)((c & 1) * 4) * GT_BYTES;
        const uint32_t aAhi = base;
        const uint32_t aAlo = base + GT_BYTES;
        const uint32_t aBhi = base + 2 * GT_BYTES;
        const uint32_t aBlo = base + 3 * GT_BYTES;

#pragma unroll
        for (int kf = 0; kf < 2; kf++) {
            uint32_t ahi[4][4], alo[4][4], bhi[2][4], blo[2][4];
#pragma unroll
            for (int mi = 0; mi < 4; mi++) {
                int row = wm + mi * 16 + (sub & 1) * 8 + r8;
                int col = kf * 16 + (sub >> 1) * 8;
                uint32_t off = (uint32_t)(row * TSTR + col) * 2;
                LDMX4(ahi[mi], aAhi + off);
                LDMX4(alo[mi], aAlo + off);
            }
#pragma unroll
            for (int np = 0; np < 2; np++) {
                int row = wn + np * 16 + (sub >> 1) * 8 + r8;
                int col = kf * 16 + (sub & 1) * 8;
                uint32_t off = (uint32_t)(row * TSTR + col) * 2;
                LDMX4(bhi[np], aBhi + off);
                LDMX4(blo[np], aBlo + off);
            }
#pragma unroll
            for (int mi = 0; mi < 4; mi++)
#pragma unroll
                for (int ni = 0; ni < 4; ni++) {
                    const uint32_t h0 = bhi[ni >> 1][(ni & 1) * 2];
                    const uint32_t h1 = bhi[ni >> 1][(ni & 1) * 2 + 1];
                    const uint32_t l0 = blo[ni >> 1][(ni & 1) * 2];
                    const uint32_t l1 = blo[ni >> 1][(ni & 1) * 2 + 1];
                    MMA16816(d[mi][ni], ahi[mi], h0, h1);
                    MMA16816(d[mi][ni], ahi[mi], l0, l1);
                    MMA16816(d[mi][ni], alo[mi], h0, h1);
                }
        }
        if (more) G_COMMIT((c + 1) & 1);
        __syncthreads();
    }
#undef G_FETCH
#undef G_COMMIT

    // ---- epilogue ----
    const int er = lane >> 2, ec = (lane & 3) * 2;
#pragma unroll
    for (int mi = 0; mi < 4; mi++)
#pragma unroll
        for (int ni = 0; ni < 4; ni++) {
            const int col = bn + wn + ni * 8 + ec;
#pragma unroll
            for (int half = 0; half < 2; half++) {
                const int row = bm + wm + mi * 16 + er + half * 8;
                float2 v = make_float2(d[mi][ni][half * 2], d[mi][ni][half * 2 + 1]);
                if (MODE == MODE_RES) {
                    float2 e = *(const float2*)(extra + (size_t)row * N + col);
                    v.x += e.x; v.y += e.y;
                    *(float2*)(Cf + (size_t)row * N + col) = v;
                } else if (MODE == MODE_BRES) {
                    float2 e = *(const float2*)(extra + (size_t)row * N + col);
                    v.x += bias[col] + e.x;
                    v.y += bias[col + 1] + e.y;
                    *(float2*)(Cf + (size_t)row * N + col) = v;
                } else {
                    if (MODE == MODE_BRELU) {
                        v.x = fmaxf(v.x + bias[col], 0.f);
                        v.y = fmaxf(v.y + bias[col + 1], 0.f);
                    }
                    __nv_bfloat162 h = __floats2bfloat162_rn(v.x, v.y);
                    float2 hf = __bfloat1622float2(h);
                    __nv_bfloat162 lo = __floats2bfloat162_rn(v.x - hf.x, v.y - hf.y);
                    *(uint32_t*)(Ch + (size_t)row * N + col) = *(uint32_t*)&h;
                    *(uint32_t*)(Cl + (size_t)row * N + col) = *(uint32_t*)&lo;
                }
            }
        }
}

template <int MODE>
__global__ __launch_bounds__(256, 1) void mma_gemm(
    const bf16* __restrict__ Ah, const bf16* __restrict__ Al,
    const bf16* __restrict__ Bh, const bf16* __restrict__ Bl,
    float* __restrict__ Cf, bf16* __restrict__ Ch, bf16* __restrict__ Cl,
    int N, int K, const float* __restrict__ bias, const float* __restrict__ extra)
{
    gemm_core<MODE>(Ah, Al, Bh, Bl, Cf, Ch, Cl, N, K, bias, extra);
}

__global__ __launch_bounds__(256, 1) void mma_qkv(
    const bf16* __restrict__ Ah, const bf16* __restrict__ Al,
    const bf16* wqh, const bf16* wql, const bf16* wkh, const bf16* wkl,
    const bf16* wvh, const bf16* wvl,
    bf16* qh, bf16* ql, bf16* kh, bf16* kl, bf16* vh, bf16* vl)
{
    const bf16* Bh = (blockIdx.z == 0) ? wqh : (blockIdx.z == 1) ? wkh : wvh;
    const bf16* Bl = (blockIdx.z == 0) ? wql : (blockIdx.z == 1) ? wkl : wvl;
    bf16* Ch = (blockIdx.z == 0) ? qh : (blockIdx.z == 1) ? kh : vh;
    bf16* Cl = (blockIdx.z == 0) ? ql : (blockIdx.z == 1) ? kl : vl;
    gemm_core<MODE_BF16>(Ah, Al, Bh, Bl, nullptr, Ch, Cl, EMB, EMB, nullptr, nullptr);
}

// ==================== HMMA flash attention (single-buffered LDG) ===========
#define FTSTR 72
#define FT_HALFS (128 * FTSTR)
#define FT_BYTES (FT_HALFS * 2)        // 18432
#define FLASH_DSMEM (3 * FT_BYTES)     // {Khi, Klo, V} = 55296

__global__ __launch_bounds__(256, 1) void flash_hmma(
    const bf16* __restrict__ Qh, const bf16* __restrict__ Ql,
    const bf16* __restrict__ Kh, const bf16* __restrict__ Kl,
    const bf16* __restrict__ Vh,
    bf16* __restrict__ Oh, bf16* __restrict__ Ol)
{
    extern __shared__ char smraw[];
    bf16* smem = (bf16*)smraw;
    const uint32_t smb = smem_u32(smraw);
    const int tid = threadIdx.x;
    const int lane = tid & 31;
    const int wid = tid >> 5;
    const int sub = lane >> 3, r8 = lane & 7;
    const int er = lane >> 2, ec = (lane & 3) * 2;
    const int wm = wid * 16;
    const int q0 = blockIdx.x * 128;
    const int hoff = blockIdx.y * DHEAD;
    const float rscale = 0.03608439182435161f;  // 1/sqrt(768)

    // copy coords: 128x64 halfs per tile = 1024 uint4, 4 per thread
    const int fr = tid >> 1;              // row pair base: 0..127
    const int fs = (tid & 1) * 8;         // 0 or 8 halfs

    // ---- stage Q hi/lo into Khi/Klo slots, extract fragments ----
#pragma unroll
    for (int i = 0; i < 4; i++) {
        int idx = i * 256 + tid;          // 0..1023
        int row = idx >> 3;
        int seg = (idx & 7) * 8;
        uint4 vh4 = *(const uint4*)(Qh + (size_t)(q0 + row) * EMB + hoff + seg);
        uint4 vl4 = *(const uint4*)(Ql + (size_t)(q0 + row) * EMB + hoff + seg);
        int off = row * FTSTR + seg;
        *(uint2*)(smem + off)                = make_uint2(vh4.x, vh4.y);
        *(uint2*)(smem + off + 4)            = make_uint2(vh4.z, vh4.w);
        *(uint2*)(smem + FT_HALFS + off)     = make_uint2(vl4.x, vl4.y);
        *(uint2*)(smem + FT_HALFS + off + 4) = make_uint2(vl4.z, vl4.w);
    }
    __syncthreads();

    uint32_t qhi[4][4], qlo[4][4];
#pragma unroll
    for (int kf = 0; kf < 4; kf++) {
        uint32_t off = (uint32_t)((wm + (sub & 1) * 8 + r8) * FTSTR
                                  + kf * 16 + (sub >> 1) * 8) * 2;
        LDMX4(qhi[kf], smb + off);
        LDMX4(qlo[kf], smb + FT_BYTES + off);
    }
    __syncthreads();   // everyone done reading Q before K overwrites

    float o[8][4];
#pragma unroll
    for (int i = 0; i < 8; i++)
#pragma unroll
        for (int j = 0; j < 4; j++) o[i][j] = 0.f;
    float m0 = -INFINITY, m1 = -INFINITY, l0 = 0.f, l1 = 0.f;

    for (int kb = 0; kb < NSEQ; kb += 128) {
        // ---- load Khi, Klo, V tiles (plain LDG -> STS, no conversion) ----
#pragma unroll
        for (int i = 0; i < 4; i++) {
            int idx = i * 256 + tid;
            int row = idx >> 3;
            int seg = (idx & 7) * 8;
            size_t goff = (size_t)(kb + row) * EMB + hoff + seg;
            int off = row * FTSTR + seg;
            uint4 a = *(const uint4*)(Kh + goff);
            uint4 b = *(const uint4*)(Kl + goff);
            uint4 c = *(const uint4*)(Vh + goff);
            *(uint2*)(smem + off)                    = make_uint2(a.x, a.y);
            *(uint2*)(smem + off + 4)                = make_uint2(a.z, a.w);
            *(uint2*)(smem + FT_HALFS + off)         = make_uint2(b.x, b.y);
            *(uint2*)(smem + FT_HALFS + off + 4)     = make_uint2(b.z, b.w);
            *(uint2*)(smem + 2 * FT_HALFS + off)     = make_uint2(c.x, c.y);
            *(uint2*)(smem + 2 * FT_HALFS + off + 4) = make_uint2(c.z, c.w);
        }
        __syncthreads();

        const uint32_t aKhi = smb;
        const uint32_t aKlo = smb + FT_BYTES;
        const uint32_t aVt  = smb + 2 * FT_BYTES;

        // ---- S = Q*K^T (3-pass hi/lo) ----
        float s[16][4];
#pragma unroll
        for (int ni = 0; ni < 16; ni++)
#pragma unroll
            for (int j = 0; j < 4; j++) s[ni][j] = 0.f;

#pragma unroll
        for (int kf = 0; kf < 4; kf++) {
#pragma unroll
            for (int np = 0; np < 8; np++) {
                uint32_t bh[4], bl[4];
                uint32_t off = (uint32_t)((np * 16 + (sub >> 1) * 8 + r8) * FTSTR
                                          + kf * 16 + (sub & 1) * 8) * 2;
                LDMX4(bh, aKhi + off);
                LDMX4(bl, aKlo + off);
                MMA16816(s[2 * np],     qhi[kf], bh[0], bh[1]);
                MMA16816(s[2 * np],     qhi[kf], bl[0], bl[1]);
                MMA16816(s[2 * np],     qlo[kf], bh[0], bh[1]);
                MMA16816(s[2 * np + 1], qhi[kf], bh[2], bh[3]);
                MMA16816(s[2 * np + 1], qhi[kf], bl[2], bl[3]);
                MMA16816(s[2 * np + 1], qlo[kf], bh[2], bh[3]);
            }
        }

        // ---- scale logits, online softmax ----
        float mx0 = -INFINITY, mx1 = -INFINITY;
#pragma unroll
        for (int ni = 0; ni < 16; ni++) {
            s[ni][0] *= rscale; s[ni][1] *= rscale;
            s[ni][2] *= rscale; s[ni][3] *= rscale;
            mx0 = fmaxf(mx0, fmaxf(s[ni][0], s[ni][1]));
            mx1 = fmaxf(mx1, fmaxf(s[ni][2], s[ni][3]));
        }
#pragma unroll
        for (int msk = 1; msk < 4; msk <<= 1) {
            mx0 = fmaxf(mx0, __shfl_xor_sync(0xffffffffu, mx0, msk));
            mx1 = fmaxf(mx1, __shfl_xor_sync(0xffffffffu, mx1, msk));
        }
        float mn0 = fmaxf(m0, mx0), mn1 = fmaxf(m1, mx1);
        float c0 = __expf(m0 - mn0), c1 = __expf(m1 - mn1);
        float rs0 = 0.f, rs1 = 0.f;
#pragma unroll
        for (int ni = 0; ni < 16; ni++) {
            s[ni][0] = __expf(s[ni][0] - mn0); rs0 += s[ni][0];
            s[ni][1] = __expf(s[ni][1] - mn0); rs0 += s[ni][1];
            s[ni][2] = __expf(s[ni][2] - mn1); rs1 += s[ni][2];
            s[ni][3] = __expf(s[ni][3] - mn1); rs1 += s[ni][3];
        }
#pragma unroll
        for (int msk = 1; msk < 4; msk <<= 1) {
            rs0 += __shfl_xor_sync(0xffffffffu, rs0, msk);
            rs1 += __shfl_xor_sync(0xffffffffu, rs1, msk);
        }
        l0 = l0 * c0 + rs0;
        l1 = l1 * c1 + rs1;
        m0 = mn0; m1 = mn1;
#pragma unroll
        for (int nd = 0; nd < 8; nd++) {
            o[nd][0] *= c0; o[nd][1] *= c0;
            o[nd][2] *= c1; o[nd][3] *= c1;
        }

        // ---- O += P*V (P packed from accum regs; V plain bf16) ----
#pragma unroll
        for (int kq = 0; kq < 8; kq++) {
            uint32_t pa[4];
            __nv_bfloat162 t;
            t = __floats2bfloat162_rn(s[2 * kq][0],     s[2 * kq][1]);     pa[0] = *(uint32_t*)&t;
            t = __floats2bfloat162_rn(s[2 * kq][2],     s[2 * kq][3]);     pa[1] = *(uint32_t*)&t;
            t = __floats2bfloat162_rn(s[2 * kq + 1][0], s[2 * kq + 1][1]); pa[2] = *(uint32_t*)&t;
            t = __floats2bfloat162_rn(s[2 * kq + 1][2], s[2 * kq + 1][3]); pa[3] = *(uint32_t*)&t;
#pragma unroll
            for (int nd16 = 0; nd16 < 4; nd16++) {
                uint32_t vb[4];
                uint32_t off = (uint32_t)((kq * 16 + (sub & 1) * 8 + r8) * FTSTR
                                          + nd16 * 16 + (sub >> 1) * 8) * 2;
                LDMX4T(vb, aVt + off);
                MMA16816(o[nd16 * 2],     pa, vb[0], vb[1]);
                MMA16816(o[nd16 * 2 + 1], pa, vb[2], vb[3]);
            }
        }
        __syncthreads();
    }

    // ---- write O as hi/lo bf16 planes ----
    const float inv0 = 1.0f / l0, inv1 = 1.0f / l1;
    const int row0 = q0 + wm + er, row1 = row0 + 8;
#pragma unroll
    for (int nd = 0; nd < 8; nd++) {
        const int col = hoff + nd * 8 + ec;
        float2 a0 = make_float2(o[nd][0] * inv0, o[nd][1] * inv0);
        float2 a1 = make_float2(o[nd][2] * inv1, o[nd][3] * inv1);
        __nv_bfloat162 h0 = __floats2bfloat162_rn(a0.x, a0.y);
        __nv_bfloat162 h1 = __floats2bfloat162_rn(a1.x, a1.y);
        float2 hf0 = __bfloat1622float2(h0);
        float2 hf1 = __bfloat1622float2(h1);
        __nv_bfloat162 lo0 = __floats2bfloat162_rn(a0.x - hf0.x, a0.y - hf0.y);
        __nv_bfloat162 lo1 = __floats2bfloat162_rn(a1.x - hf1.x, a1.y - hf1.y);
        *(uint32_t*)(Oh + (size_t)row0 * EMB + col) = *(uint32_t*)&h0;
        *(uint32_t*)(Ol + (size_t)row0 * EMB + col) = *(uint32_t*)&lo0;
        *(uint32_t*)(Oh + (size_t)row1 * EMB + col) = *(uint32_t*)&h1;
        *(uint32_t*)(Ol + (size_t)row1 * EMB + col) = *(uint32_t*)&lo1;
    }
}

// -------------------- fp32 SGEMM (embed only: trunc is discontinuous) ------
__global__ __launch_bounds__(256, 1) void sgemm_embed(
    const float* __restrict__ A, const float* __restrict__ B, float* __restrict__ C,
    bf16* __restrict__ Ch, bf16* __restrict__ Cl,
    int M, int N, int K, const float* __restrict__ bias, const float* __restrict__ extra)
{
    __shared__ float As[8][128];
    __shared__ float Bs[8][128];
    const int tid = threadIdx.x;
    const int bm = blockIdx.y * 128;
    const int bn = blockIdx.x * 128;
    const int lr = tid & 127;
    const int lc = (tid >> 7) << 2;
    const float* Ap = A + (size_t)(bm + lr) * K + lc;
    const float* Bp = B + (size_t)(bn + lr) * K + lc;
    const int tx = tid & 15, ty = tid >> 4;

    float acc[8][8];
#pragma unroll
    for (int i = 0; i < 8; i++)
#pragma unroll
        for (int j = 0; j < 8; j++) acc[i][j] = 0.f;

    for (int k0 = 0; k0 < K; k0 += 8) {
        float4 a4 = *(const float4*)(Ap + k0);
        float4 b4 = *(const float4*)(Bp + k0);
        As[lc + 0][lr] = a4.x; As[lc + 1][lr] = a4.y;
        As[lc + 2][lr] = a4.z; As[lc + 3][lr] = a4.w;
        Bs[lc + 0][lr] = b4.x; Bs[lc + 1][lr] = b4.y;
        Bs[lc + 2][lr] = b4.z; Bs[lc + 3][lr] = b4.w;
        __syncthreads();
#pragma unroll
        for (int k = 0; k < 8; k++) {
            float ra[8], rb[8];
            *(float4*)(ra)     = *(const float4*)&As[k][ty * 8];
            *(float4*)(ra + 4) = *(const float4*)&As[k][ty * 8 + 4];
            *(float4*)(rb)     = *(const float4*)&Bs[k][tx * 8];
            *(float4*)(rb + 4) = *(const float4*)&Bs[k][tx * 8 + 4];
#pragma unroll
            for (int i = 0; i < 8; i++)
#pragma unroll
                for (int j = 0; j < 8; j++)
                    acc[i][j] = fmaf(ra[i], rb[j], acc[i][j]);
        }
        __syncthreads();
    }

#pragma unroll
    for (int i = 0; i < 8; i++) {
        const int r = bm + ty * 8 + i;
#pragma unroll
        for (int j = 0; j < 8; j++) {
            const int c = bn + tx * 8 + j;
            float v = truncf(acc[i][j] + bias[c]) + extra[(size_t)r * N + c];
            C[(size_t)r * N + c] = v;
            bf16 h = __float2bfloat16(v);
            Ch[(size_t)r * N + c] = h;
            Cl[(size_t)r * N + c] = __float2bfloat16(v - __bfloat162float(h));
        }
    }
}

// -------------------- layernorm (fp32 + hi/lo outputs) ---------------------
__global__ __launch_bounds__(256, 1) void ln_kernel(
    const float* __restrict__ in, float* __restrict__ out,
    bf16* __restrict__ outh, bf16* __restrict__ outl,
    const float* __restrict__ g, const float* __restrict__ b)
{
    __shared__ float rs[8], rs2[8];
    __shared__ float s_mu, s_rstd;
    const int r = blockIdx.x;
    const int tid = threadIdx.x;
    const float* row = in + (size_t)r * EMB;
    float v0 = row[tid], v1 = row[tid + 256], v2 = row[tid + 512];
    float s = v0 + v1 + v2;
    float s2 = v0 * v0 + v1 * v1 + v2 * v2;
#pragma unroll
    for (int m = 16; m; m >>= 1) {
        s += __shfl_xor_sync(0xffffffffu, s, m);
        s2 += __shfl_xor_sync(0xffffffffu, s2, m);
    }
    if ((tid & 31) == 0) { rs[tid >> 5] = s; rs2[tid >> 5] = s2; }
    __syncthreads();
    if (tid == 0) {
        float S = 0.f, S2 = 0.f;
#pragma unroll
        for (int i = 0; i < 8; i++) { S += rs[i]; S2 += rs2[i]; }
        float mu = S * (1.0f / EMB);
        float var = S2 * (1.0f / EMB) - mu * mu;
        s_mu = mu;
        s_rstd = rsqrtf(var + 1e-5f);
    }
    __syncthreads();
    float mu = s_mu, rstd = s_rstd;
#pragma unroll
    for (int seg = 0; seg < 3; seg++) {
        int c = tid + seg * 256;
        float v = (seg == 0) ? v0 : (seg == 1) ? v1 : v2;
        float y = (v - mu) * rstd * g[c] + b[c];
        out[(size_t)r * EMB + c] = y;
        bf16 h = __float2bfloat16(y);
        outh[(size_t)r * EMB + c] = h;
        outl[(size_t)r * EMB + c] = __float2bfloat16(y - __bfloat162float(h));
    }
}

// -------------------- mean over sequence -----------------------------------
__global__ void mean_kernel(const float* __restrict__ in, float* __restrict__ out)
{
    int e = blockIdx.x * 256 + threadIdx.x;
    float s = 0.f;
    for (int n = 0; n < NSEQ; n++) s += in[(size_t)n * EMB + e];
    out[e] = s * (1.0f / NSEQ);
}

// -------------------- launch ------------------------------------------------
extern "C" void kernel_launch(void* const* d_in, const int* in_sizes, int n_in,
                              void* d_out, int out_size)
{
    (void)in_sizes; (void)n_in; (void)out_size;
    const float* x      = (const float*)d_in[0];
    const float* W_word = (const float*)d_in[2];
    const float* b_word = (const float*)d_in[3];
    const float* pos    = (const float*)d_in[4];
    const float* Wq     = (const float*)d_in[5];
    const float* Wk     = (const float*)d_in[6];
    const float* Wv     = (const float*)d_in[7];
    const float* Wo     = (const float*)d_in[8];
    const float* W1     = (const float*)d_in[9];
    const float* b1     = (const float*)d_in[10];
    const float* W2     = (const float*)d_in[11];
    const float* b2     = (const float*)d_in[12];
    const float* g1     = (const float*)d_in[13];
    const float* be1    = (const float*)d_in[14];
    const float* g2     = (const float*)d_in[15];
    const float* be2    = (const float*)d_in[16];
    float* out = (float*)d_out;

    float *p_out, *p_tmp, *p_xm;
    bf16 *p_out_h, *p_out_l, *p_xm_h, *p_xm_l;
    bf16 *p_q_h, *p_q_l, *p_k_h, *p_k_l, *p_v_h, *p_v_l, *p_att_h, *p_att_l;
    bf16 *p_ff_h, *p_ff_l;
    bf16 *p_wq_h, *p_wq_l, *p_wk_h, *p_wk_l, *p_wv_h, *p_wv_l;
    bf16 *p_wo_h, *p_wo_l, *p_w1_h, *p_w1_l, *p_w2_h, *p_w2_l;
    cudaGetSymbolAddress((void**)&p_out, g_out);
    cudaGetSymbolAddress((void**)&p_tmp, g_tmp);
    cudaGetSymbolAddress((void**)&p_xm,  g_xm);
    cudaGetSymbolAddress((void**)&p_out_h, g_out_h); cudaGetSymbolAddress((void**)&p_out_l, g_out_l);
    cudaGetSymbolAddress((void**)&p_xm_h,  g_xm_h);  cudaGetSymbolAddress((void**)&p_xm_l,  g_xm_l);
    cudaGetSymbolAddress((void**)&p_q_h,   g_q_h);   cudaGetSymbolAddress((void**)&p_q_l,   g_q_l);
    cudaGetSymbolAddress((void**)&p_k_h,   g_k_h);   cudaGetSymbolAddress((void**)&p_k_l,   g_k_l);
    cudaGetSymbolAddress((void**)&p_v_h,   g_v_h);   cudaGetSymbolAddress((void**)&p_v_l,   g_v_l);
    cudaGetSymbolAddress((void**)&p_att_h, g_att_h); cudaGetSymbolAddress((void**)&p_att_l, g_att_l);
    cudaGetSymbolAddress((void**)&p_ff_h,  g_ff_h);  cudaGetSymbolAddress((void**)&p_ff_l,  g_ff_l);
    cudaGetSymbolAddress((void**)&p_wq_h, g_wq_h);   cudaGetSymbolAddress((void**)&p_wq_l, g_wq_l);
    cudaGetSymbolAddress((void**)&p_wk_h, g_wk_h);   cudaGetSymbolAddress((void**)&p_wk_l, g_wk_l);
    cudaGetSymbolAddress((void**)&p_wv_h, g_wv_h);   cudaGetSymbolAddress((void**)&p_wv_l, g_wv_l);
    cudaGetSymbolAddress((void**)&p_wo_h, g_wo_h);   cudaGetSymbolAddress((void**)&p_wo_l, g_wo_l);
    cudaGetSymbolAddress((void**)&p_w1_h, g_w1_h);   cudaGetSymbolAddress((void**)&p_w1_l, g_w1_l);
    cudaGetSymbolAddress((void**)&p_w2_h, g_w2_h);   cudaGetSymbolAddress((void**)&p_w2_l, g_w2_l);

    cudaFuncSetAttribute(mma_gemm<MODE_RES>,   cudaFuncAttributeMaxDynamicSharedMemorySize, GEMM_DSMEM);
    cudaFuncSetAttribute(mma_gemm<MODE_BRELU>, cudaFuncAttributeMaxDynamicSharedMemorySize, GEMM_DSMEM);
    cudaFuncSetAttribute(mma_gemm<MODE_BRES>,  cudaFuncAttributeMaxDynamicSharedMemorySize, GEMM_DSMEM);
    cudaFuncSetAttribute(mma_qkv,              cudaFuncAttributeMaxDynamicSharedMemorySize, GEMM_DSMEM);
    cudaFuncSetAttribute(flash_hmma,           cudaFuncAttributeMaxDynamicSharedMemorySize, FLASH_DSMEM);

    // ---- split weights into hi/lo planes (once per launch) ----
    {
        int nee4 = NLAYER * EMB * EMB / 4;
        int nfe4 = NLAYER * FFDIM * EMB / 4;
        conv_split<<<(nee4 + 255) / 256, 256>>>(Wq, p_wq_h, p_wq_l, nee4);
        conv_split<<<(nee4 + 255) / 256, 256>>>(Wk, p_wk_h, p_wk_l, nee4);
        conv_split<<<(nee4 + 255) / 256, 256>>>(Wv, p_wv_h, p_wv_l, nee4);
        conv_split<<<(nee4 + 255) / 256, 256>>>(Wo, p_wo_h, p_wo_l, nee4);
        conv_split<<<(nfe4 + 255) / 256, 256>>>(W1, p_w1_h, p_w1_l, nfe4);
        conv_split<<<(nfe4 + 255) / 256, 256>>>(W2, p_w2_h, p_w2_l, nfe4);
    }

    dim3 blk(256);
    dim3 gEE(EMB / 128, NSEQ / 128);       // 6 x 24
    dim3 gQKV(EMB / 128, NSEQ / 128, 3);   // 6 x 24 x 3
    dim3 gFF(FFDIM / 128, NSEQ / 128);     // 24 x 24
    dim3 gFL(NSEQ / 128, NHEAD);           // 24 x 12

    // embed: out = trunc(x @ Ww^T + b_word) + pos (fp32 + hi/lo planes)
    sgemm_embed<<<gEE, blk>>>(x, W_word, p_out, p_out_h, p_out_l,
                              NSEQ, EMB, EMB, b_word, pos);

    for (int l = 0; l < NLAYER; l++) {
        const size_t oEE = (size_t)l * EMB * EMB;
        const size_t oFE = (size_t)l * FFDIM * EMB;

        mma_qkv<<<gQKV, blk, GEMM_DSMEM>>>(
            p_out_h, p_out_l,
            p_wq_h + oEE, p_wq_l + oEE, p_wk_h + oEE, p_wk_l + oEE,
            p_wv_h + oEE, p_wv_l + oEE,
            p_q_h, p_q_l, p_k_h, p_k_l, p_v_h, p_v_l);

        flash_hmma<<<gFL, blk, FLASH_DSMEM>>>(
            p_q_h, p_q_l, p_k_h, p_k_l, p_v_h, p_att_h, p_att_l);

        mma_gemm<MODE_RES><<<gEE, blk, GEMM_DSMEM>>>(
            p_att_h, p_att_l, p_wo_h + oEE, p_wo_l + oEE,
            p_tmp, nullptr, nullptr, EMB, EMB, nullptr, p_out);
        ln_kernel<<<NSEQ, 256>>>(p_tmp, p_xm, p_xm_h, p_xm_l,
                                 g1 + (size_t)l * EMB, be1 + (size_t)l * EMB);

        mma_gemm<MODE_BRELU><<<gFF, blk, GEMM_DSMEM>>>(
            p_xm_h, p_xm_l, p_w1_h + oFE, p_w1_l + oFE,
            nullptr, p_ff_h, p_ff_l, FFDIM, EMB, b1 + (size_t)l * FFDIM, nullptr);
        mma_gemm<MODE_BRES><<<gEE, blk, GEMM_DSMEM>>>(
            p_ff_h, p_ff_l, p_w2_h + oFE, p_w2_l + oFE,
            p_tmp, nullptr, nullptr, EMB, FFDIM, b2 + (size_t)l * EMB, p_xm);
        ln_kernel<<<NSEQ, 256>>>(p_tmp, p_out, p_out_h, p_out_l,
                                 g2 + (size_t)l * EMB, be2 + (size_t)l * EMB);
    }

    mean_kernel<<<3, 256>>>(p_out, out);
}